// round 1
// baseline (speedup 1.0000x reference)
#include <cuda_runtime.h>

// WindowOverlapProcessor: gather formulation.
// Grid of 63x63 windows, stride 8, win 16 over 512x512. Each output pixel is
// covered by <=2x2 windows; (win,dh,dw) -> pixel is a bijection so the
// windows tensor is streamed exactly once. Separable Gaussian weight sum
// computed on the fly; matches reference's normalized blend + 1e-8 epsilon.

#define H_    512
#define W_    512
#define WS_   16
#define STR_  8
#define HW_   63
#define NW_   (HW_ * HW_)
#define B_    8
#define C_    3
#define PLANE (H_ * W_)

__global__ void __launch_bounds__(256)
window_overlap_gather(const float* __restrict__ windows,
                      float* __restrict__ out)
{
    __shared__ float g[WS_];      // normalized 1D gaussian
    __shared__ float s_inv;

    int tid = threadIdx.x;
    if (tid < WS_) {
        float x = (float)tid - 7.5f;                 // (ws-1)/2 = 7.5
        g[tid] = expf(-(x * x) / 32.0f);             // 2*sigma^2 = 32
    }
    __syncthreads();
    if (tid == 0) {
        float s = 0.0f;
        #pragma unroll
        for (int k = 0; k < WS_; k++) s += g[k];
        s_inv = 1.0f / s;
    }
    __syncthreads();
    if (tid < WS_) g[tid] *= s_inv;                  // normalized g
    __syncthreads();

    int idx = blockIdx.x * blockDim.x + tid;         // 0 .. B*H*W-1
    int w = idx & (W_ - 1);
    int h = (idx >> 9) & (H_ - 1);
    int b = idx >> 18;

    // covering window index range: i*8 <= h <= i*8+15
    int i_lo = (h >= STR_) ? ((h - STR_) >> 3) : 0;
    int i_hi = min(HW_ - 1, h >> 3);
    int j_lo = (w >= STR_) ? ((w - STR_) >> 3) : 0;
    int j_hi = min(HW_ - 1, w >> 3);

    // separable normalized weight sum
    float sh = 0.0f, sw = 0.0f;
    #pragma unroll 2
    for (int i = i_lo; i <= i_hi; i++) sh += g[h - (i << 3)];
    #pragma unroll 2
    for (int j = j_lo; j <= j_hi; j++) sw += g[w - (j << 3)];
    float inv = 1.0f / (sh * sw + 1e-8f);

    float a0 = 0.0f, a1 = 0.0f, a2 = 0.0f;
    #pragma unroll 2
    for (int i = i_lo; i <= i_hi; i++) {
        int dh = h - (i << 3);
        float gh = g[dh];
        #pragma unroll 2
        for (int j = j_lo; j <= j_hi; j++) {
            int dw = w - (j << 3);
            float wgt = gh * g[dw];
            // windows[b][i*63+j][dh][dw][c], C=3 contiguous
            int base = (((b * NW_ + i * HW_ + j) * (WS_ * WS_)) + (dh << 4) + dw) * C_;
            a0 += wgt * __ldg(windows + base + 0);
            a1 += wgt * __ldg(windows + base + 1);
            a2 += wgt * __ldg(windows + base + 2);
        }
    }

    // out[b][c][h][w]
    int ob = b * (C_ * PLANE) + (h << 9) + w;
    out[ob]             = a0 * inv;
    out[ob + PLANE]     = a1 * inv;
    out[ob + 2 * PLANE] = a2 * inv;
}

extern "C" void kernel_launch(void* const* d_in, const int* in_sizes, int n_in,
                              void* d_out, int out_size)
{
    const float* windows = (const float*)d_in[0];
    float* out = (float*)d_out;
    // 8 * 512 * 512 = 2,097,152 threads
    int total = B_ * H_ * W_;
    window_overlap_gather<<<total / 256, 256>>>(windows, out);
}

// round 2
// speedup vs baseline: 1.3031x; 1.3031x over previous
#include <cuda_runtime.h>

// WindowOverlapProcessor: vectorized gather.
// One thread per (b, h, 4-aligned group of 4 w pixels). For a 4-aligned group
// the covering-window j-set {k-1,k} (k=w4>>3) is uniform across the group and
// each window contributes 12 contiguous, 16B-aligned floats (4 px x 3 ch)
// -> 3x LDG.128 per window, <=2x2 windows, 3x STG.128 out.

#define H_    512
#define W_    512
#define WS_   16
#define STR_  8
#define HW_   63
#define NW_   (HW_ * HW_)
#define B_    8
#define C_    3
#define PLANE (H_ * W_)

__global__ void __launch_bounds__(256)
window_overlap_gather_v4(const float* __restrict__ windows,
                         float* __restrict__ out)
{
    __shared__ float g[WS_];      // normalized 1D gaussian
    __shared__ float s_inv;

    int tid = threadIdx.x;
    if (tid < WS_) {
        float x = (float)tid - 7.5f;                 // (ws-1)/2
        g[tid] = expf(-(x * x) / 32.0f);             // 2*sigma^2 = 32
    }
    __syncthreads();
    if (tid == 0) {
        float s = 0.0f;
        #pragma unroll
        for (int k = 0; k < WS_; k++) s += g[k];
        s_inv = 1.0f / s;
    }
    __syncthreads();
    if (tid < WS_) g[tid] *= s_inv;
    __syncthreads();

    int gid = blockIdx.x * blockDim.x + tid;   // 0 .. B*H*(W/4)-1 = 524287
    int wg = gid & 127;                        // w-group index, 128 per row
    int h  = (gid >> 7) & 511;
    int b  = gid >> 16;
    int w4 = wg << 2;

    int kh = h >> 3;
    int kw = w4 >> 3;

    // normalized weight sums (separable)
    float sh = 0.0f;
    #pragma unroll
    for (int ii = 0; ii < 2; ii++) {
        int i = kh - 1 + ii;
        if (i >= 0 && i <= HW_ - 1) sh += g[h - (i << 3)];
    }
    float sw0 = 0.f, sw1 = 0.f, sw2 = 0.f, sw3 = 0.f;
    #pragma unroll
    for (int jj = 0; jj < 2; jj++) {
        int j = kw - 1 + jj;
        if (j >= 0 && j <= HW_ - 1) {
            int dw0 = w4 - (j << 3);          // in {0,4,8,12}
            sw0 += g[dw0];  sw1 += g[dw0 + 1];
            sw2 += g[dw0 + 2]; sw3 += g[dw0 + 3];
        }
    }
    float inv0 = 1.0f / (sh * sw0 + 1e-8f);
    float inv1 = 1.0f / (sh * sw1 + 1e-8f);
    float inv2 = 1.0f / (sh * sw2 + 1e-8f);
    float inv3 = 1.0f / (sh * sw3 + 1e-8f);

    // accumulators: a[p][c] for 4 pixels x 3 channels
    float a00=0,a01=0,a02=0, a10=0,a11=0,a12=0;
    float a20=0,a21=0,a22=0, a30=0,a31=0,a32=0;

    #pragma unroll
    for (int ii = 0; ii < 2; ii++) {
        int i = kh - 1 + ii;
        if (i < 0 || i > HW_ - 1) continue;
        int dh = h - (i << 3);                // in [0,15]
        float gh = g[dh];
        #pragma unroll
        for (int jj = 0; jj < 2; jj++) {
            int j = kw - 1 + jj;
            if (j < 0 || j > HW_ - 1) continue;
            int dw0 = w4 - (j << 3);          // {0,4,8,12}
            // float offset = ((b*NW + i*63 + j)*256 + dh*16 + dw0) * 3
            long off = ((long)(b * NW_ + i * HW_ + j) << 8) + (dh << 4) + dw0;
            const float4* p = (const float4*)(windows + off * 3);
            float4 v0 = p[0], v1 = p[1], v2 = p[2];
            float wt0 = gh * g[dw0];
            float wt1 = gh * g[dw0 + 1];
            float wt2 = gh * g[dw0 + 2];
            float wt3 = gh * g[dw0 + 3];
            // layout: v0 = {p0c0,p0c1,p0c2,p1c0} v1 = {p1c1,p1c2,p2c0,p2c1}
            //         v2 = {p2c2,p3c0,p3c1,p3c2}
            a00 += wt0 * v0.x; a01 += wt0 * v0.y; a02 += wt0 * v0.z;
            a10 += wt1 * v0.w; a11 += wt1 * v1.x; a12 += wt1 * v1.y;
            a20 += wt2 * v1.z; a21 += wt2 * v1.w; a22 += wt2 * v2.x;
            a30 += wt3 * v2.y; a31 += wt3 * v2.z; a32 += wt3 * v2.w;
        }
    }

    // out[b][c][h][w4..w4+3], contiguous 16B-aligned per channel
    float* ob = out + b * (C_ * PLANE) + (h << 9) + w4;
    *(float4*)(ob)             = make_float4(a00*inv0, a10*inv1, a20*inv2, a30*inv3);
    *(float4*)(ob + PLANE)     = make_float4(a01*inv0, a11*inv1, a21*inv2, a31*inv3);
    *(float4*)(ob + 2*PLANE)   = make_float4(a02*inv0, a12*inv1, a22*inv2, a32*inv3);
}

extern "C" void kernel_launch(void* const* d_in, const int* in_sizes, int n_in,
                              void* d_out, int out_size)
{
    const float* windows = (const float*)d_in[0];
    float* out = (float*)d_out;
    int total = B_ * H_ * (W_ / 4);   // 524288 threads
    window_overlap_gather_v4<<<total / 256, 256>>>(windows, out);
}

// round 3
// speedup vs baseline: 1.4112x; 1.0830x over previous
#include <cuda_runtime.h>

// WindowOverlapProcessor: vectorized gather, branch-free edition.
// One thread per (b, h, 4-aligned w group). Boundary windows handled by
// clamping the window index (address stays in-bounds) and zeroing the
// Gaussian weight, so all 12 LDG.128 are unconditional and front-batched
// -> MLP=12 per thread, DRAM latency fully hidden.

#define H_    512
#define W_    512
#define WS_   16
#define HW_   63
#define NW_   (HW_ * HW_)
#define B_    8
#define C_    3
#define PLANE (H_ * W_)

__global__ void __launch_bounds__(256)
window_overlap_gather_v4b(const float* __restrict__ windows,
                          float* __restrict__ out)
{
    __shared__ float g[WS_];      // normalized 1D gaussian

    int tid = threadIdx.x;
    if (tid < WS_) {
        float x = (float)tid - 7.5f;
        g[tid] = expf(-(x * x) / 32.0f);
    }
    __syncthreads();
    if (tid == 0) {
        float s = 0.0f;
        #pragma unroll
        for (int k = 0; k < WS_; k++) s += g[k];
        float si = 1.0f / s;
        #pragma unroll
        for (int k = 0; k < WS_; k++) g[k] *= si;
    }
    __syncthreads();

    int gid = blockIdx.x * blockDim.x + tid;   // 0 .. B*H*(W/4)-1
    int w4 = (gid & 127) << 2;
    int h  = (gid >> 7) & 511;
    int b  = gid >> 16;

    int kh = h >> 3;
    int kw = w4 >> 3;

    // clamped window indices + validity
    int i0r = kh - 1, i1r = kh;
    int j0r = kw - 1, j1r = kw;
    int i0 = max(i0r, 0), i1 = min(i1r, HW_ - 1);
    int j0 = max(j0r, 0), j1 = min(j1r, HW_ - 1);
    bool vi0 = (i0r >= 0), vi1 = (i1r <= HW_ - 1);
    bool vj0 = (j0r >= 0), vj1 = (j1r <= HW_ - 1);

    // clamped local offsets (always in range by construction)
    int dh0 = h - (i0 << 3), dh1 = h - (i1 << 3);      // [0,15]
    int dwA = w4 - (j0 << 3), dwB = w4 - (j1 << 3);    // {0,4,8,12}

    // ---- front-batched loads: 4 windows x 3 float4, no control deps ----
    long bb = (long)b * NW_;
    const float4* p00 = (const float4*)(windows + 3 * (((bb + i0 * HW_ + j0) << 8) + (dh0 << 4) + dwA));
    const float4* p01 = (const float4*)(windows + 3 * (((bb + i0 * HW_ + j1) << 8) + (dh0 << 4) + dwB));
    const float4* p10 = (const float4*)(windows + 3 * (((bb + i1 * HW_ + j0) << 8) + (dh1 << 4) + dwA));
    const float4* p11 = (const float4*)(windows + 3 * (((bb + i1 * HW_ + j1) << 8) + (dh1 << 4) + dwB));

    float4 v00a = p00[0], v00b = p00[1], v00c = p00[2];
    float4 v01a = p01[0], v01b = p01[1], v01c = p01[2];
    float4 v10a = p10[0], v10b = p10[1], v10c = p10[2];
    float4 v11a = p11[0], v11b = p11[1], v11c = p11[2];

    // ---- weights (overlaps load latency) ----
    float gh0 = vi0 ? g[dh0] : 0.0f;
    float gh1 = vi1 ? g[dh1] : 0.0f;
    float gwA0 = vj0 ? g[dwA]     : 0.0f;
    float gwA1 = vj0 ? g[dwA + 1] : 0.0f;
    float gwA2 = vj0 ? g[dwA + 2] : 0.0f;
    float gwA3 = vj0 ? g[dwA + 3] : 0.0f;
    float gwB0 = vj1 ? g[dwB]     : 0.0f;
    float gwB1 = vj1 ? g[dwB + 1] : 0.0f;
    float gwB2 = vj1 ? g[dwB + 2] : 0.0f;
    float gwB3 = vj1 ? g[dwB + 3] : 0.0f;

    float sh = gh0 + gh1;
    float inv0 = 1.0f / (sh * (gwA0 + gwB0) + 1e-8f);
    float inv1 = 1.0f / (sh * (gwA1 + gwB1) + 1e-8f);
    float inv2 = 1.0f / (sh * (gwA2 + gwB2) + 1e-8f);
    float inv3 = 1.0f / (sh * (gwA3 + gwB3) + 1e-8f);

    // ---- accumulate: 4 px x 3 ch ----
    // layout per window: vXa={p0c0,p0c1,p0c2,p1c0} vXb={p1c1,p1c2,p2c0,p2c1}
    //                    vXc={p2c2,p3c0,p3c1,p3c2}
    float a00, a01, a02, a10, a11, a12, a20, a21, a22, a30, a31, a32;
    {
        float w0 = gh0 * gwA0, w1 = gh0 * gwA1, w2 = gh0 * gwA2, w3 = gh0 * gwA3;
        a00 = w0 * v00a.x; a01 = w0 * v00a.y; a02 = w0 * v00a.z;
        a10 = w1 * v00a.w; a11 = w1 * v00b.x; a12 = w1 * v00b.y;
        a20 = w2 * v00b.z; a21 = w2 * v00b.w; a22 = w2 * v00c.x;
        a30 = w3 * v00c.y; a31 = w3 * v00c.z; a32 = w3 * v00c.w;
    }
    {
        float w0 = gh0 * gwB0, w1 = gh0 * gwB1, w2 = gh0 * gwB2, w3 = gh0 * gwB3;
        a00 += w0 * v01a.x; a01 += w0 * v01a.y; a02 += w0 * v01a.z;
        a10 += w1 * v01a.w; a11 += w1 * v01b.x; a12 += w1 * v01b.y;
        a20 += w2 * v01b.z; a21 += w2 * v01b.w; a22 += w2 * v01c.x;
        a30 += w3 * v01c.y; a31 += w3 * v01c.z; a32 += w3 * v01c.w;
    }
    {
        float w0 = gh1 * gwA0, w1 = gh1 * gwA1, w2 = gh1 * gwA2, w3 = gh1 * gwA3;
        a00 += w0 * v10a.x; a01 += w0 * v10a.y; a02 += w0 * v10a.z;
        a10 += w1 * v10a.w; a11 += w1 * v10b.x; a12 += w1 * v10b.y;
        a20 += w2 * v10b.z; a21 += w2 * v10b.w; a22 += w2 * v10c.x;
        a30 += w3 * v10c.y; a31 += w3 * v10c.z; a32 += w3 * v10c.w;
    }
    {
        float w0 = gh1 * gwB0, w1 = gh1 * gwB1, w2 = gh1 * gwB2, w3 = gh1 * gwB3;
        a00 += w0 * v11a.x; a01 += w0 * v11a.y; a02 += w0 * v11a.z;
        a10 += w1 * v11a.w; a11 += w1 * v11b.x; a12 += w1 * v11b.y;
        a20 += w2 * v11b.z; a21 += w2 * v11b.w; a22 += w2 * v11c.x;
        a30 += w3 * v11c.y; a31 += w3 * v11c.z; a32 += w3 * v11c.w;
    }

    float* ob = out + b * (C_ * PLANE) + (h << 9) + w4;
    *(float4*)(ob)           = make_float4(a00 * inv0, a10 * inv1, a20 * inv2, a30 * inv3);
    *(float4*)(ob + PLANE)   = make_float4(a01 * inv0, a11 * inv1, a21 * inv2, a31 * inv3);
    *(float4*)(ob + 2*PLANE) = make_float4(a02 * inv0, a12 * inv1, a22 * inv2, a32 * inv3);
}

extern "C" void kernel_launch(void* const* d_in, const int* in_sizes, int n_in,
                              void* d_out, int out_size)
{
    const float* windows = (const float*)d_in[0];
    float* out = (float*)d_out;
    int total = B_ * H_ * (W_ / 4);   // 524288 threads
    window_overlap_gather_v4b<<<total / 256, 256>>>(windows, out);
}